// round 6
// baseline (speedup 1.0000x reference)
#include <cuda_runtime.h>
#include <cstdint>
#include <math.h>
#include <cstdio>
#include <cstdlib>

#define NBATCH 16
#define RPB    1024
#define MROW   (NBATCH*RPB)
#define KDIM   512
#define NSLOT  5
#define NPB    (RPB*KDIM)
#define NPB4   (NPB/4)
#define GRAM_CHUNKS 32
#define BODY_BLOCKS (8*256)
#define LAMBDA 1e-4
#define TOLV   0.01

__device__ __align__(16) float  g_Fm[NBATCH*NSLOT*NPB];
__device__ __align__(16) float  g_G [NBATCH*NSLOT*NPB];
__device__ __align__(16) float  g_xlast[MROW*KDIM];
__device__ double g_gram_part[NBATCH*GRAM_CHUNKS*15];
__device__ double g_res_part[BODY_BLOCKS*2];
__device__ float  g_alpha[NBATCH*NSLOT];
__device__ int    g_converged;
__device__ double g_diag[1024];

__global__ void resetK() {
    g_converged = 0;
    g_diag[20] = -1.0;   // convergence k
    g_diag[21] = 0.0;    // max solve residual
    g_diag[22] = 0.0;    // max |alpha|
}

// fp64 recompute of f(x) row0/row777 vs g_Fm slot0 (cheap GEMM self-check)
__global__ void checkInitK(const float* A, const float* W, const float* Bv)
{
    __shared__ double mx[512];
    int c = threadIdx.x;
    for (int rsel = 0; rsel < 2; rsel++) {
        int r = rsel ? 777 : 0;
        double acc = (double)Bv[c];
        for (int k = 0; k < 512; k++)
            acc = fma((double)A[(size_t)r*512+k], (double)W[(size_t)c*512+k], acc);
        double got = (double)g_Fm[(size_t)r*512 + c];
        mx[c] = fabs(acc - got); __syncthreads();
        for (int s = 256; s > 0; s >>= 1) { if (c < s && mx[c+s] > mx[c]) mx[c] = mx[c+s]; __syncthreads(); }
        if (c == 0) g_diag[11 + rsel] = mx[0];
        __syncthreads();
    }
}

// ---------------------------------------------------------------------------
// Fused GEMM (64x64 tile, BK=16, 256 thr, 4x4 microtile)
// ---------------------------------------------------------------------------
__global__ __launch_bounds__(256) void gemm512(
    const float* __restrict__ A, int aMode, int aSlot,
    const float* __restrict__ W, const float* __restrict__ bias,
    float* __restrict__ outPlain, int outSlot, int doRes, int doGuard)
{
    if (doGuard && g_converged) return;

    __shared__ __align__(16) float As[16][68];
    __shared__ __align__(16) float Bs[16][68];
    __shared__ double sred[256];

    const int tid = threadIdx.x;
    const int m0  = blockIdx.y * 64;
    const int n0  = blockIdx.x * 64;
    const int ty  = tid >> 4, tx = tid & 15;
    const int lr  = tid >> 2;
    const int lk  = (tid & 3) << 2;

    const int gr = m0 + lr;
    const float* aRow;
    if (aMode == 1) {
        int b = gr >> 10, rr = gr & 1023;
        aRow = g_Fm + ((size_t)(b*NSLOT + aSlot))*NPB + (size_t)rr*KDIM;
    } else if (aMode == 2) {
        aRow = g_xlast + (size_t)gr*KDIM;
    } else {
        aRow = A + (size_t)gr*KDIM;
    }
    const float* wRow = W + (size_t)(n0 + lr)*KDIM;

    float acc[4][4];
#pragma unroll
    for (int i = 0; i < 4; i++)
#pragma unroll
        for (int j = 0; j < 4; j++) acc[i][j] = 0.f;

    for (int k0 = 0; k0 < KDIM; k0 += 16) {
        float4 av = *(const float4*)(aRow + k0 + lk);
        float4 bv = *(const float4*)(wRow + k0 + lk);
        As[lk+0][lr]=av.x; As[lk+1][lr]=av.y; As[lk+2][lr]=av.z; As[lk+3][lr]=av.w;
        Bs[lk+0][lr]=bv.x; Bs[lk+1][lr]=bv.y; Bs[lk+2][lr]=bv.z; Bs[lk+3][lr]=bv.w;
        __syncthreads();
#pragma unroll
        for (int k = 0; k < 16; k++) {
            float4 a4 = *(const float4*)&As[k][ty << 2];
            float4 b4 = *(const float4*)&Bs[k][tx << 2];
            float ar[4] = {a4.x, a4.y, a4.z, a4.w};
            float br[4] = {b4.x, b4.y, b4.z, b4.w};
#pragma unroll
            for (int i = 0; i < 4; i++)
#pragma unroll
                for (int j = 0; j < 4; j++)
                    acc[i][j] = fmaf(ar[i], br[j], acc[i][j]);
        }
        __syncthreads();
    }

    double sn = 0.0, sd = 0.0;
#pragma unroll
    for (int i = 0; i < 4; i++) {
        const int r = m0 + (ty << 2) + i;
        const float* aR;
        if (aMode == 1) {
            int b = r >> 10, rr = r & 1023;
            aR = g_Fm + ((size_t)(b*NSLOT + aSlot))*NPB + (size_t)rr*KDIM;
        } else if (aMode == 2) {
            aR = g_xlast + (size_t)r*KDIM;
        } else {
            aR = A + (size_t)r*KDIM;
        }
#pragma unroll
        for (int j = 0; j < 4; j++) {
            const int c = n0 + (tx << 2) + j;
            float val = acc[i][j] + bias[c];
            if (outSlot >= 0) {
                int b = r >> 10, rr = r & 1023;
                size_t o = ((size_t)(b*NSLOT + outSlot))*NPB + (size_t)rr*KDIM + c;
                float av2 = aR[c];
                g_Fm[o] = val;
                g_G[o]  = val - av2;
                if (doRes) {
                    float d = val - av2;
                    sn += (double)d * (double)d;
                    sd += (double)val * (double)val;
                }
            } else {
                outPlain[(size_t)r*KDIM + c] = val;
            }
        }
    }

    if (doRes) {
        sred[tid] = sn; __syncthreads();
        for (int s = 128; s > 0; s >>= 1) { if (tid < s) sred[tid] += sred[tid+s]; __syncthreads(); }
        double tsn = sred[0]; __syncthreads();
        sred[tid] = sd; __syncthreads();
        for (int s = 128; s > 0; s >>= 1) { if (tid < s) sred[tid] += sred[tid+s]; __syncthreads(); }
        if (tid == 0) {
            int bid = blockIdx.y * gridDim.x + blockIdx.x;
            g_res_part[2*bid]   = tsn;
            g_res_part[2*bid+1] = sred[0];
        }
    }
}

// ---------------------------------------------------------------------------
__global__ __launch_bounds__(256) void gramK(int nk)
{
    if (g_converged) return;
    const int tid = threadIdx.x;
    const int b = blockIdx.y;
    const int chunk = blockIdx.x;
    const float4* Gb = ((const float4*)g_G) + (size_t)b*NSLOT*NPB4;

    double s[15];
#pragma unroll
    for (int p = 0; p < 15; p++) s[p] = 0.0;

    for (int t = 0; t < 16; t++) {
        int f = chunk*4096 + t*256 + tid;
        float4 gv[5];
#pragma unroll
        for (int i = 0; i < 5; i++)
            gv[i] = (i < nk) ? Gb[(size_t)i*NPB4 + f] : make_float4(0.f,0.f,0.f,0.f);
        int p = 0;
#pragma unroll
        for (int i = 0; i < 5; i++)
#pragma unroll
            for (int j = i; j < 5; j++) {
                float d = gv[i].x*gv[j].x + gv[i].y*gv[j].y
                        + gv[i].z*gv[j].z + gv[i].w*gv[j].w;
                s[p++] += (double)d;
            }
    }

    __shared__ double sh[256];
    for (int p = 0; p < 15; p++) {
        sh[tid] = s[p]; __syncthreads();
        for (int st = 128; st > 0; st >>= 1) { if (tid < st) sh[tid] += sh[tid+st]; __syncthreads(); }
        if (tid == 0) g_gram_part[((size_t)(b*GRAM_CHUNKS + chunk))*15 + p] = sh[0];
        __syncthreads();
    }
}

// ---------------------------------------------------------------------------
// Anderson alpha via Cholesky + normalization (equivalent to bordered KKT):
//   z = (Gram_active + lambda I)^{-1} 1 ;  alpha = z / sum(z)  (sum(z) > 0 PSD)
// Sum(alpha) = 1 by construction.
// ---------------------------------------------------------------------------
__global__ void solveK(int nk, int kIter)
{
    if (g_converged) return;
    int b = threadIdx.x;
    if (b >= NBATCH) return;

    double gram[15];
    for (int p = 0; p < 15; p++) gram[p] = 0.0;
    for (int c = 0; c < GRAM_CHUNKS; c++)
        for (int p = 0; p < 15; p++)
            gram[p] += g_gram_part[((size_t)(b*GRAM_CHUNKS + c))*15 + p];

    // Build full symmetric active matrix
    double Afull[5][5];
    {
        int p = 0;
        for (int i = 0; i < 5; i++)
            for (int j = i; j < 5; j++) {
                double v = gram[p++];
                Afull[i][j] = v; Afull[j][i] = v;
            }
        for (int i = 0; i < 5; i++) Afull[i][i] += LAMBDA;
    }

    // Cholesky (lower) on leading nk x nk
    double L[5][5];
    for (int c = 0; c < nk; c++) {
        double d = Afull[c][c];
        for (int q = 0; q < c; q++) d -= L[c][q]*L[c][q];
        d = sqrt(fmax(d, 1e-300));
        L[c][c] = d;
        for (int r = c+1; r < nk; r++) {
            double v = Afull[r][c];
            for (int q = 0; q < c; q++) v -= L[r][q]*L[c][q];
            L[r][c] = v / d;
        }
    }
    // L y = 1
    double y[5];
    for (int r = 0; r < nk; r++) {
        double v = 1.0;
        for (int j = 0; j < r; j++) v -= L[r][j]*y[j];
        y[r] = v / L[r][r];
    }
    // L^T z = y
    double z[5];
    for (int r = nk-1; r >= 0; r--) {
        double v = y[r];
        for (int j = r+1; j < nk; j++) v -= L[j][r]*z[j];
        z[r] = v / L[r][r];
    }
    double S = 0.0;
    for (int r = 0; r < nk; r++) S += z[r];
    double al[5];
    for (int m = 0; m < 5; m++) al[m] = (m < nk) ? z[m]/S : 0.0;
    for (int m = 0; m < 5; m++) g_alpha[b*5 + m] = (float)al[m];

    // verification: residual of (A z = 1) on active block, and max|alpha|
    double rmax = 0.0, amax = 0.0;
    for (int r = 0; r < nk; r++) {
        double v = 0.0;
        for (int j = 0; j < nk; j++) v += Afull[r][j]*z[j];
        double rr = fabs(v - 1.0);
        if (rr > rmax) rmax = rr;
        if (fabs(al[r]) > amax) amax = fabs(al[r]);
    }
    if (b == 0) {
        double* d = g_diag + 40 + (size_t)(kIter - 2)*12;
        d[0]=al[0]; d[1]=al[1]; d[2]=al[2]; d[3]=al[3]; d[4]=al[4];
        d[5]=S; d[6]=gram[0]; d[7]=gram[5]; d[8]=gram[9]; d[9]=gram[14];
        if (rmax > g_diag[21]) g_diag[21] = rmax;
        if (amax > g_diag[22]) g_diag[22] = amax;
    }
}

// ---------------------------------------------------------------------------
__global__ __launch_bounds__(256) void comboK(int nk)
{
    if (g_converged) return;
    int f = blockIdx.x*256 + threadIdx.x;
    int b = f >> 17;
    int off = f & (NPB4 - 1);
    const float4* Fb = ((const float4*)g_Fm) + (size_t)b*NSLOT*NPB4;
    float4 acc = make_float4(0.f,0.f,0.f,0.f);
#pragma unroll
    for (int m = 0; m < 5; m++) {
        if (m < nk) {
            float al = g_alpha[b*5 + m];
            float4 v = Fb[(size_t)m*NPB4 + off];
            acc.x = fmaf(al, v.x, acc.x);
            acc.y = fmaf(al, v.y, acc.y);
            acc.z = fmaf(al, v.z, acc.z);
            acc.w = fmaf(al, v.w, acc.w);
        }
    }
    ((float4*)g_xlast)[f] = acc;
}

// ---------------------------------------------------------------------------
__global__ __launch_bounds__(256) void reduceResK(int kIter)
{
    if (g_converged) return;
    int tid = threadIdx.x;
    double sn = 0.0, sd = 0.0;
    for (int i = tid; i < BODY_BLOCKS; i += 256) {
        sn += g_res_part[2*i];
        sd += g_res_part[2*i+1];
    }
    __shared__ double sh[256];
    sh[tid] = sn; __syncthreads();
    for (int s = 128; s > 0; s >>= 1) { if (tid < s) sh[tid] += sh[tid+s]; __syncthreads(); }
    double tsn = sh[0]; __syncthreads();
    sh[tid] = sd; __syncthreads();
    for (int s = 128; s > 0; s >>= 1) { if (tid < s) sh[tid] += sh[tid+s]; __syncthreads(); }
    if (tid == 0) {
        double nn = sqrt(tsn), dd = sqrt(sh[0]);
        double res = nn / (1e-5 + dd);
        double* d = g_diag + 700 + (size_t)(kIter - 2)*4;
        d[0] = res; d[1] = nn; d[2] = dd; d[3] = (double)g_xlast[0];
        if (res < TOLV) { g_converged = 1; g_diag[20] = (double)kIter; }
    }
}

// ---------------------------------------------------------------------------
extern "C" void kernel_launch(void* const* d_in, const int* in_sizes, int n_in,
                              void* d_out, int out_size)
{
    const float* x      = (const float*)d_in[0];
    const float* lin_w  = (const float*)d_in[1];
    const float* lin_b  = (const float*)d_in[2];
    const float* weight = (const float*)d_in[3];
    const float* bias   = (const float*)d_in[4];
    float* out = (float*)d_out;

    cudaStreamCaptureStatus cap = cudaStreamCaptureStatusNone;
    cudaStreamIsCapturing(0, &cap);
    const bool capturing = (cap != cudaStreamCaptureStatusNone);

    dim3 gg(8, 256);

    resetK<<<1, 1>>>();

    gemm512<<<gg, 256>>>(x,       0, 0, lin_w, lin_b, nullptr, 0, 0, 0);
    checkInitK<<<1, 512>>>(x, lin_w, lin_b);
    gemm512<<<gg, 256>>>(nullptr, 1, 0, lin_w, lin_b, nullptr, 1, 0, 0);

    for (int k = 2; k < 50; k++) {
        int nk  = (k < 5) ? k : 5;
        int idx = k % 5;
        gramK   <<<dim3(GRAM_CHUNKS, NBATCH), 256>>>(nk);
        solveK  <<<1, 32>>>(nk, k);
        comboK  <<<8192, 256>>>(nk);
        gemm512 <<<gg, 256>>>(nullptr, 2, 0, lin_w, lin_b, nullptr, idx, 1, 1);
        reduceResK<<<1, 256>>>(k);
    }

    gemm512<<<gg, 256>>>(nullptr, 2, 0, weight, bias, out, -1, 0, 0);

    // Diagnostics only on non-captured (correctness) calls; identical device
    // work either way. Dump + abort ONLY if the solver failed to converge.
    if (!capturing) {
        cudaDeviceSynchronize();
        static double h[1024];
        cudaMemcpyFromSymbol(h, g_diag, sizeof(h));
        if (h[20] < 0.0) {
            // print k descending so truncation (keeps tail) preserves early k
            for (int k = 49; k >= 2; k--) {
                double* a = h + 40 + (size_t)(k-2)*12;
                double* r = h + 700 + (size_t)(k-2)*4;
                fprintf(stderr,
                  "D k=%d res=%.3e nn=%.2e dd=%.2e xl0=%.4f a=[%.2f %.2f %.2f %.2f %.2f] S=%.3e g=[%.2e %.2e %.2e %.2e]\n",
                  k, r[0], r[1], r[2], r[3], a[0], a[1], a[2], a[3], a[4],
                  a[5], a[6], a[7], a[8], a[9]);
            }
            fprintf(stderr,
              "D SUMMARY convk=%.0f solveres=%.3e amax=%.3e initchk=[%.3e %.3e]\n",
              h[20], h[21], h[22], h[11], h[12]);
            fflush(stderr);
            exit(42);
        }
    }
}

// round 7
// speedup vs baseline: 1.2396x; 1.2396x over previous
#include <cuda_runtime.h>
#include <cstdint>
#include <math.h>
#include <cstdio>
#include <cstdlib>

#define NBATCH 16
#define RPB    1024
#define MROW   (NBATCH*RPB)
#define KDIM   512
#define NSLOT  5
#define NPB    (RPB*KDIM)
#define NPB4   (NPB/4)
#define GRAM_CHUNKS 32
#define BODY_BLOCKS 512             // gemm grid = 4 x 128
#define LAMBDA 1e-4
#define TOLV   0.01

__device__ __align__(16) float  g_Fm[NBATCH*NSLOT*NPB];
__device__ __align__(16) float  g_G [NBATCH*NSLOT*NPB];
__device__ __align__(16) float  g_xlast[MROW*KDIM];
__device__ double g_gram_part[NBATCH*GRAM_CHUNKS*15];
__device__ double g_res_part[BODY_BLOCKS*2];
__device__ float  g_alpha[NBATCH*NSLOT];
__device__ int    g_converged;
__device__ double g_diag[1024];

__global__ void resetK() {
    g_converged = 0;
    g_diag[20] = -1.0;
    g_diag[21] = 0.0;
    g_diag[22] = 0.0;
}

// ---- packed f32x2 helpers (sm_103a) ----------------------------------------
__device__ __forceinline__ unsigned long long pk2(float x, float y) {
    unsigned long long r;
    asm("mov.b64 %0, {%1, %2};" : "=l"(r) : "f"(x), "f"(y));
    return r;
}
__device__ __forceinline__ void upk2(unsigned long long v, float& x, float& y) {
    asm("mov.b64 {%0, %1}, %2;" : "=f"(x), "=f"(y) : "l"(v));
}
__device__ __forceinline__ void ffma2(unsigned long long& d,
                                      unsigned long long a, unsigned long long b) {
    asm("fma.rn.f32x2 %0, %1, %2, %0;" : "+l"(d) : "l"(a), "l"(b));
}

// ---------------------------------------------------------------------------
// GEMM: out[r,c] = sum_k A[r,k]*W[c,k] + bias[c]
// 128x128 block tile, BK=16, 256 threads, 8x8 microtile (4+4 split rows/cols),
// packed f32x2 FMAs (row-paired accumulators).
//   aMode: 0 = A param, 1 = g_Fm slot aSlot, 2 = g_xlast
//   outSlot >= 0: write g_Fm[slot], g_G[slot] = val - A; optional residual
//   outSlot <  0: write outPlain
// ---------------------------------------------------------------------------
#define BM 128
#define BN 128
#define BK 16

__device__ __forceinline__ const float* resolveRow(const float* A, int aMode,
                                                   int aSlot, int r) {
    if (aMode == 1) {
        int b = r >> 10, rr = r & 1023;
        return g_Fm + ((size_t)(b*NSLOT + aSlot))*NPB + (size_t)rr*KDIM;
    } else if (aMode == 2) {
        return g_xlast + (size_t)r*KDIM;
    }
    return A + (size_t)r*KDIM;
}

__global__ __launch_bounds__(256, 2) void gemm128(
    const float* __restrict__ A, int aMode, int aSlot,
    const float* __restrict__ W, const float* __restrict__ bias,
    float* __restrict__ outPlain, int outSlot, int doRes, int doGuard)
{
    if (doGuard && g_converged) return;

    __shared__ __align__(16) float As[BK][BM];
    __shared__ __align__(16) float Bs[BK][BN];
    __shared__ double sred[256];

    const int tid = threadIdx.x;
    const int m0  = blockIdx.y * BM;
    const int n0  = blockIdx.x * BN;
    const int tx  = tid & 15;          // col group 0..15
    const int ty  = tid >> 4;          // row group 0..15

    // loader mapping: each thread loads 8 k-values for one row of A and one of W
    const int lr = tid >> 1;           // 0..127
    const int lk = (tid & 1) << 3;     // 0 or 8

    const float* aRow = resolveRow(A, aMode, aSlot, m0 + lr);
    const float* wRow = W + (size_t)(n0 + lr)*KDIM;

    unsigned long long acc[4][8];
#pragma unroll
    for (int ip = 0; ip < 4; ip++)
#pragma unroll
        for (int j = 0; j < 8; j++) acc[ip][j] = 0ULL;

    // prefetch tile 0
    float4 pa0 = *(const float4*)(aRow + lk);
    float4 pa1 = *(const float4*)(aRow + lk + 4);
    float4 pb0 = *(const float4*)(wRow + lk);
    float4 pb1 = *(const float4*)(wRow + lk + 4);

    for (int k0 = 0; k0 < KDIM; k0 += BK) {
        // stage prefetched tile
        As[lk+0][lr]=pa0.x; As[lk+1][lr]=pa0.y; As[lk+2][lr]=pa0.z; As[lk+3][lr]=pa0.w;
        As[lk+4][lr]=pa1.x; As[lk+5][lr]=pa1.y; As[lk+6][lr]=pa1.z; As[lk+7][lr]=pa1.w;
        Bs[lk+0][lr]=pb0.x; Bs[lk+1][lr]=pb0.y; Bs[lk+2][lr]=pb0.z; Bs[lk+3][lr]=pb0.w;
        Bs[lk+4][lr]=pb1.x; Bs[lk+5][lr]=pb1.y; Bs[lk+6][lr]=pb1.z; Bs[lk+7][lr]=pb1.w;
        __syncthreads();

        if (k0 + BK < KDIM) {
            pa0 = *(const float4*)(aRow + k0 + BK + lk);
            pa1 = *(const float4*)(aRow + k0 + BK + lk + 4);
            pb0 = *(const float4*)(wRow + k0 + BK + lk);
            pb1 = *(const float4*)(wRow + k0 + BK + lk + 4);
        }

#pragma unroll
        for (int kk = 0; kk < BK; kk++) {
            // row pairs: rows {ty*4, ty*4+1}, {ty*4+2, +3}, {64+ty*4, +1}, {64+ty*4+2, +3}
            float2 a0 = *(const float2*)&As[kk][ty*4];
            float2 a1 = *(const float2*)&As[kk][ty*4 + 2];
            float2 a2 = *(const float2*)&As[kk][64 + ty*4];
            float2 a3 = *(const float2*)&As[kk][64 + ty*4 + 2];
            float4 b03 = *(const float4*)&Bs[kk][tx*4];
            float4 b47 = *(const float4*)&Bs[kk][64 + tx*4];

            unsigned long long ap[4];
            ap[0] = pk2(a0.x, a0.y); ap[1] = pk2(a1.x, a1.y);
            ap[2] = pk2(a2.x, a2.y); ap[3] = pk2(a3.x, a3.y);
            unsigned long long bb[8];
            bb[0]=pk2(b03.x,b03.x); bb[1]=pk2(b03.y,b03.y);
            bb[2]=pk2(b03.z,b03.z); bb[3]=pk2(b03.w,b03.w);
            bb[4]=pk2(b47.x,b47.x); bb[5]=pk2(b47.y,b47.y);
            bb[6]=pk2(b47.z,b47.z); bb[7]=pk2(b47.w,b47.w);

#pragma unroll
            for (int ip = 0; ip < 4; ip++)
#pragma unroll
                for (int j = 0; j < 8; j++)
                    ffma2(acc[ip][j], ap[ip], bb[j]);
        }
        __syncthreads();
    }

    // epilogue
    double sn = 0.0, sd = 0.0;
#pragma unroll
    for (int ip = 0; ip < 4; ip++) {
        const int rbase = ((ip & 2) ? 64 : 0) + ty*4 + ((ip & 1) ? 2 : 0);
#pragma unroll
        for (int half = 0; half < 2; half++) {
            const int r = m0 + rbase + half;
            const float* aR = resolveRow(A, aMode, aSlot, r);
            int b = r >> 10, rr = r & 1023;
            size_t obase = ((size_t)(b*NSLOT + outSlot))*NPB + (size_t)rr*KDIM;
#pragma unroll
            for (int j = 0; j < 8; j++) {
                const int c = n0 + ((j < 4) ? (tx*4 + j) : (64 + tx*4 + j - 4));
                float lo, hi;
                upk2(acc[ip][j], lo, hi);
                float v = half ? hi : lo;
                float val = v + bias[c];
                if (outSlot >= 0) {
                    float av2 = aR[c];
                    g_Fm[obase + c] = val;
                    g_G [obase + c] = val - av2;
                    if (doRes) {
                        float d = val - av2;
                        sn += (double)d * (double)d;
                        sd += (double)val * (double)val;
                    }
                } else {
                    outPlain[(size_t)r*KDIM + c] = val;
                }
            }
        }
    }

    if (doRes) {
        sred[tid] = sn; __syncthreads();
        for (int s = 128; s > 0; s >>= 1) { if (tid < s) sred[tid] += sred[tid+s]; __syncthreads(); }
        double tsn = sred[0]; __syncthreads();
        sred[tid] = sd; __syncthreads();
        for (int s = 128; s > 0; s >>= 1) { if (tid < s) sred[tid] += sred[tid+s]; __syncthreads(); }
        if (tid == 0) {
            int bid = blockIdx.y * gridDim.x + blockIdx.x;
            g_res_part[2*bid]   = tsn;
            g_res_part[2*bid+1] = sred[0];
        }
    }
}

// ---------------------------------------------------------------------------
__global__ __launch_bounds__(256) void gramK(int nk)
{
    if (g_converged) return;
    const int tid = threadIdx.x;
    const int b = blockIdx.y;
    const int chunk = blockIdx.x;
    const float4* Gb = ((const float4*)g_G) + (size_t)b*NSLOT*NPB4;

    double s[15];
#pragma unroll
    for (int p = 0; p < 15; p++) s[p] = 0.0;

    for (int t = 0; t < 16; t++) {
        int f = chunk*4096 + t*256 + tid;
        float4 gv[5];
#pragma unroll
        for (int i = 0; i < 5; i++)
            gv[i] = (i < nk) ? Gb[(size_t)i*NPB4 + f] : make_float4(0.f,0.f,0.f,0.f);
        int p = 0;
#pragma unroll
        for (int i = 0; i < 5; i++)
#pragma unroll
            for (int j = i; j < 5; j++) {
                float d = gv[i].x*gv[j].x + gv[i].y*gv[j].y
                        + gv[i].z*gv[j].z + gv[i].w*gv[j].w;
                s[p++] += (double)d;
            }
    }

    __shared__ double sh[256];
    for (int p = 0; p < 15; p++) {
        sh[tid] = s[p]; __syncthreads();
        for (int st = 128; st > 0; st >>= 1) { if (tid < st) sh[tid] += sh[tid+st]; __syncthreads(); }
        if (tid == 0) g_gram_part[((size_t)(b*GRAM_CHUNKS + chunk))*15 + p] = sh[0];
        __syncthreads();
    }
}

// ---------------------------------------------------------------------------
// alpha = normalize( (Gram_active + lambda I)^{-1} 1 )   [== bordered KKT]
// ---------------------------------------------------------------------------
__global__ void solveK(int nk, int kIter)
{
    if (g_converged) return;
    int b = threadIdx.x;
    if (b >= NBATCH) return;

    double gram[15];
    for (int p = 0; p < 15; p++) gram[p] = 0.0;
    for (int c = 0; c < GRAM_CHUNKS; c++)
        for (int p = 0; p < 15; p++)
            gram[p] += g_gram_part[((size_t)(b*GRAM_CHUNKS + c))*15 + p];

    double Afull[5][5];
    {
        int p = 0;
        for (int i = 0; i < 5; i++)
            for (int j = i; j < 5; j++) {
                double v = gram[p++];
                Afull[i][j] = v; Afull[j][i] = v;
            }
        for (int i = 0; i < 5; i++) Afull[i][i] += LAMBDA;
    }

    double L[5][5];
    for (int c = 0; c < nk; c++) {
        double d = Afull[c][c];
        for (int q = 0; q < c; q++) d -= L[c][q]*L[c][q];
        d = sqrt(fmax(d, 1e-300));
        L[c][c] = d;
        for (int r = c+1; r < nk; r++) {
            double v = Afull[r][c];
            for (int q = 0; q < c; q++) v -= L[r][q]*L[c][q];
            L[r][c] = v / d;
        }
    }
    double y[5];
    for (int r = 0; r < nk; r++) {
        double v = 1.0;
        for (int j = 0; j < r; j++) v -= L[r][j]*y[j];
        y[r] = v / L[r][r];
    }
    double z[5];
    for (int r = nk-1; r >= 0; r--) {
        double v = y[r];
        for (int j = r+1; j < nk; j++) v -= L[j][r]*z[j];
        z[r] = v / L[r][r];
    }
    double S = 0.0;
    for (int r = 0; r < nk; r++) S += z[r];
    double al[5];
    for (int m = 0; m < 5; m++) al[m] = (m < nk) ? z[m]/S : 0.0;
    for (int m = 0; m < 5; m++) g_alpha[b*5 + m] = (float)al[m];

    if (b == 0) {
        double* d = g_diag + 40 + (size_t)(kIter - 2)*12;
        d[0]=al[0]; d[1]=al[1]; d[2]=al[2]; d[3]=al[3]; d[4]=al[4];
        d[5]=S; d[6]=gram[0]; d[7]=gram[5]; d[8]=gram[9]; d[9]=gram[14];
    }
}

// ---------------------------------------------------------------------------
__global__ __launch_bounds__(256) void comboK(int nk)
{
    if (g_converged) return;
    int f = blockIdx.x*256 + threadIdx.x;
    int b = f >> 17;
    int off = f & (NPB4 - 1);
    const float4* Fb = ((const float4*)g_Fm) + (size_t)b*NSLOT*NPB4;
    float4 acc = make_float4(0.f,0.f,0.f,0.f);
#pragma unroll
    for (int m = 0; m < 5; m++) {
        if (m < nk) {
            float al = g_alpha[b*5 + m];
            float4 v = Fb[(size_t)m*NPB4 + off];
            acc.x = fmaf(al, v.x, acc.x);
            acc.y = fmaf(al, v.y, acc.y);
            acc.z = fmaf(al, v.z, acc.z);
            acc.w = fmaf(al, v.w, acc.w);
        }
    }
    ((float4*)g_xlast)[f] = acc;
}

// ---------------------------------------------------------------------------
__global__ __launch_bounds__(256) void reduceResK(int kIter)
{
    if (g_converged) return;
    int tid = threadIdx.x;
    double sn = 0.0, sd = 0.0;
    for (int i = tid; i < BODY_BLOCKS; i += 256) {
        sn += g_res_part[2*i];
        sd += g_res_part[2*i+1];
    }
    __shared__ double sh[256];
    sh[tid] = sn; __syncthreads();
    for (int s = 128; s > 0; s >>= 1) { if (tid < s) sh[tid] += sh[tid+s]; __syncthreads(); }
    double tsn = sh[0]; __syncthreads();
    sh[tid] = sd; __syncthreads();
    for (int s = 128; s > 0; s >>= 1) { if (tid < s) sh[tid] += sh[tid+s]; __syncthreads(); }
    if (tid == 0) {
        double nn = sqrt(tsn), dd = sqrt(sh[0]);
        double res = nn / (1e-5 + dd);
        double* d = g_diag + 700 + (size_t)(kIter - 2)*4;
        d[0] = res; d[1] = nn; d[2] = dd; d[3] = (double)g_xlast[0];
        if (res < TOLV) { g_converged = 1; g_diag[20] = (double)kIter; }
    }
}

// ---------------------------------------------------------------------------
extern "C" void kernel_launch(void* const* d_in, const int* in_sizes, int n_in,
                              void* d_out, int out_size)
{
    const float* x      = (const float*)d_in[0];
    const float* lin_w  = (const float*)d_in[1];
    const float* lin_b  = (const float*)d_in[2];
    const float* weight = (const float*)d_in[3];
    const float* bias   = (const float*)d_in[4];
    float* out = (float*)d_out;

    cudaStreamCaptureStatus cap = cudaStreamCaptureStatusNone;
    cudaStreamIsCapturing(0, &cap);
    const bool capturing = (cap != cudaStreamCaptureStatusNone);

    dim3 gg(KDIM/BN, MROW/BM);   // (4, 128)

    resetK<<<1, 1>>>();

    gemm128<<<gg, 256>>>(x,       0, 0, lin_w, lin_b, nullptr, 0, 0, 0);
    gemm128<<<gg, 256>>>(nullptr, 1, 0, lin_w, lin_b, nullptr, 1, 0, 0);

    for (int k = 2; k < 50; k++) {
        int nk  = (k < 5) ? k : 5;
        int idx = k % 5;
        gramK   <<<dim3(GRAM_CHUNKS, NBATCH), 256>>>(nk);
        solveK  <<<1, 32>>>(nk, k);
        comboK  <<<8192, 256>>>(nk);
        gemm128 <<<gg, 256>>>(nullptr, 2, 0, lin_w, lin_b, nullptr, idx, 1, 1);
        reduceResK<<<1, 256>>>(k);
    }

    gemm128<<<gg, 256>>>(nullptr, 2, 0, weight, bias, out, -1, 0, 0);

    // Fail-only diagnostics on non-captured calls (zero cost when converged).
    if (!capturing) {
        cudaDeviceSynchronize();
        static double h[1024];
        cudaMemcpyFromSymbol(h, g_diag, sizeof(h));
        if (h[20] < 0.0) {
            for (int k = 49; k >= 2; k--) {
                double* a = h + 40 + (size_t)(k-2)*12;
                double* r = h + 700 + (size_t)(k-2)*4;
                fprintf(stderr,
                  "D k=%d res=%.3e nn=%.2e dd=%.2e xl0=%.4f a=[%.2f %.2f %.2f %.2f %.2f] S=%.3e g=[%.2e %.2e %.2e %.2e]\n",
                  k, r[0], r[1], r[2], r[3], a[0], a[1], a[2], a[3], a[4],
                  a[5], a[6], a[7], a[8], a[9]);
            }
            fprintf(stderr, "D SUMMARY convk=%.0f\n", h[20]);
            fflush(stderr);
            exit(42);
        }
    }
}